// round 12
// baseline (speedup 1.0000x reference)
#include <cuda_runtime.h>

// AbstractRelu (DeepPoly ReLU relaxation), elementwise over N fp32.
// out layout: [relu(x) (N)] [lb_slope*low (N)] [relu(high) (N)]
//
// CONVERGED FINAL (R5/R8/R10/R11: 63.26-63.55us wall band, ~55.7us kernel,
// DRAM ~79%, 7.2 TB/s effective ~ 90% of HBM spec = B300 LTS cap).
// Search history (12 benches):
//   R1  256t float4 sequential ................ 63.7
//   R2  2-quad FRONT-BATCHED loads ............ 65.6  (L1tex queue contention)
//   R3  R1 + .cs hints ........................ 63.6  (hints neutral)
//   R4  persistent grid 1184 CTAs ............. 71.7  (regressed)
//   R5  128t float4 sequential + .cs .......... 63.3  << best
//   R6  2-quad sequential (fenced) ............ 63.8  (neutral)
//   R7  256-bit v8.f32 ld/st .................. 64.2  (issue not binding)
//   R8  R5 reproduction ....................... 63.3  (stable)
//   R9  64t probe ............................. 63.5  (flat)
//   R10 R5 reproduction ....................... 63.6  (stable)
//   R11 R5 reproduction ....................... 63.5  (stable)
// Traffic is at the 402MB floor (3 fp32 reads + 3 fp32 writes, zero reuse,
// output layout fixed by harness). Kernel is HBM-bound at the LTS/HBM
// ceiling. No remaining lever in the B300 model for this workload.

__global__ void __launch_bounds__(128, 16)
abstract_relu_kernel(const float4* __restrict__ x,
                     const float4* __restrict__ low,
                     const float4* __restrict__ high,
                     float4* __restrict__ x_out,
                     float4* __restrict__ low_out,
                     float4* __restrict__ high_out,
                     int n4)
{
    int i = blockIdx.x * blockDim.x + threadIdx.x;
    if (i >= n4) return;

    float4 xv = __ldcs(&x[i]);
    float4 lv = __ldcs(&low[i]);
    float4 hv = __ldcs(&high[i]);

    float4 xo, lo, ho;

    #define LANE(f)                                                        \
    {                                                                      \
        float xe = xv.f, le = lv.f, he = hv.f;                             \
        xo.f = fmaxf(xe, 0.0f);                                            \
        ho.f = fmaxf(he, 0.0f);                                            \
        bool zero = (he <= 0.0f) || (le < 0.0f && le * le > he * he);      \
        lo.f = zero ? 0.0f : le;                                           \
    }

    LANE(x) LANE(y) LANE(z) LANE(w)
    #undef LANE

    __stcs(&x_out[i],    xo);
    __stcs(&low_out[i],  lo);
    __stcs(&high_out[i], ho);
}

extern "C" void kernel_launch(void* const* d_in, const int* in_sizes, int n_in,
                              void* d_out, int out_size)
{
    const float* x    = (const float*)d_in[0];
    const float* low  = (const float*)d_in[1];
    const float* high = (const float*)d_in[2];
    float* out = (float*)d_out;

    const int n  = in_sizes[0];          // 16777216
    const int n4 = n / 4;                // 4194304

    float* x_out    = out;
    float* low_out  = out + n;
    float* high_out = out + 2 * (size_t)n;

    const int threads = 128;
    const int blocks  = (n4 + threads - 1) / threads;  // 32768

    abstract_relu_kernel<<<blocks, threads>>>(
        (const float4*)x, (const float4*)low, (const float4*)high,
        (float4*)x_out, (float4*)low_out, (float4*)high_out, n4);
}

// round 13
// speedup vs baseline: 1.0010x; 1.0010x over previous
#include <cuda_runtime.h>

// AbstractRelu (DeepPoly ReLU relaxation), elementwise over N fp32.
// out layout: [relu(x) (N)] [lb_slope*low (N)] [relu(high) (N)]
//
// CONVERGED FINAL (R5/R8/R10/R11/R12: 63.26-63.55us wall band, ~55.9us
// kernel, DRAM ~79%, 7.2 TB/s effective ~ 90% of HBM spec = B300 LTS cap).
// Search history (13 benches):
//   R1  256t float4 sequential ................ 63.7
//   R2  2-quad FRONT-BATCHED loads ............ 65.6  (L1tex queue contention)
//   R3  R1 + .cs hints ........................ 63.6  (hints neutral)
//   R4  persistent grid 1184 CTAs ............. 71.7  (regressed)
//   R5  128t float4 sequential + .cs .......... 63.3  << best
//   R6  2-quad sequential (fenced) ............ 63.8  (neutral)
//   R7  256-bit v8.f32 ld/st .................. 64.2  (issue not binding)
//   R8-R12 reproductions ...................... 63.3-63.6 (stable)
// Traffic is at the 402MB floor (3 fp32 reads + 3 fp32 writes, zero reuse,
// output layout fixed by harness). Kernel is HBM-bound at the LTS/HBM
// ceiling; residual DRAM-pipe headroom is R/W turnaround, not addressable
// from SASS. No remaining lever in the B300 model for this workload.

__global__ void __launch_bounds__(128, 16)
abstract_relu_kernel(const float4* __restrict__ x,
                     const float4* __restrict__ low,
                     const float4* __restrict__ high,
                     float4* __restrict__ x_out,
                     float4* __restrict__ low_out,
                     float4* __restrict__ high_out,
                     int n4)
{
    int i = blockIdx.x * blockDim.x + threadIdx.x;
    if (i >= n4) return;

    float4 xv = __ldcs(&x[i]);
    float4 lv = __ldcs(&low[i]);
    float4 hv = __ldcs(&high[i]);

    float4 xo, lo, ho;

    #define LANE(f)                                                        \
    {                                                                      \
        float xe = xv.f, le = lv.f, he = hv.f;                             \
        xo.f = fmaxf(xe, 0.0f);                                            \
        ho.f = fmaxf(he, 0.0f);                                            \
        bool zero = (he <= 0.0f) || (le < 0.0f && le * le > he * he);      \
        lo.f = zero ? 0.0f : le;                                           \
    }

    LANE(x) LANE(y) LANE(z) LANE(w)
    #undef LANE

    __stcs(&x_out[i],    xo);
    __stcs(&low_out[i],  lo);
    __stcs(&high_out[i], ho);
}

extern "C" void kernel_launch(void* const* d_in, const int* in_sizes, int n_in,
                              void* d_out, int out_size)
{
    const float* x    = (const float*)d_in[0];
    const float* low  = (const float*)d_in[1];
    const float* high = (const float*)d_in[2];
    float* out = (float*)d_out;

    const int n  = in_sizes[0];          // 16777216
    const int n4 = n / 4;                // 4194304

    float* x_out    = out;
    float* low_out  = out + n;
    float* high_out = out + 2 * (size_t)n;

    const int threads = 128;
    const int blocks  = (n4 + threads - 1) / threads;  // 32768

    abstract_relu_kernel<<<blocks, threads>>>(
        (const float4*)x, (const float4*)low, (const float4*)high,
        (float4*)x_out, (float4*)low_out, (float4*)high_out, n4);
}

// round 14
// speedup vs baseline: 1.0071x; 1.0061x over previous
#include <cuda_runtime.h>

// AbstractRelu (DeepPoly ReLU relaxation), elementwise over N fp32.
// out layout: [relu(x) (N)] [lb_slope*low (N)] [relu(high) (N)]
//
// CONVERGED FINAL (R5, verified stable R8/R10-R13: 63.26-63.55us wall band,
// ~55.8us kernel, DRAM ~79%, 7.2 TB/s effective ~ 90% of HBM spec = B300
// LTS cap). Search history (14 benches):
//   R1  256t float4 sequential ................ 63.7
//   R2  2-quad FRONT-BATCHED loads ............ 65.6  (L1tex queue contention)
//   R3  R1 + .cs hints ........................ 63.6  (hints neutral)
//   R4  persistent grid 1184 CTAs ............. 71.7  (regressed)
//   R5  128t float4 sequential + .cs .......... 63.3  << best
//   R6  2-quad sequential (fenced) ............ 63.8  (neutral)
//   R7  256-bit v8.f32 ld/st .................. 64.2  (issue not binding)
//   R8-R13 reproductions ...................... 63.3-63.6 (stable)
// Traffic is at the 402MB floor; kernel is HBM-bound at the LTS/HBM
// ceiling; residual DRAM-pipe headroom is R/W bus turnaround, not
// addressable from SASS. No remaining lever for this workload.

__global__ void __launch_bounds__(128, 16)
abstract_relu_kernel(const float4* __restrict__ x,
                     const float4* __restrict__ low,
                     const float4* __restrict__ high,
                     float4* __restrict__ x_out,
                     float4* __restrict__ low_out,
                     float4* __restrict__ high_out,
                     int n4)
{
    int i = blockIdx.x * blockDim.x + threadIdx.x;
    if (i >= n4) return;

    float4 xv = __ldcs(&x[i]);
    float4 lv = __ldcs(&low[i]);
    float4 hv = __ldcs(&high[i]);

    float4 xo, lo, ho;

    #define LANE(f)                                                        \
    {                                                                      \
        float xe = xv.f, le = lv.f, he = hv.f;                             \
        xo.f = fmaxf(xe, 0.0f);                                            \
        ho.f = fmaxf(he, 0.0f);                                            \
        bool zero = (he <= 0.0f) || (le < 0.0f && le * le > he * he);      \
        lo.f = zero ? 0.0f : le;                                           \
    }

    LANE(x) LANE(y) LANE(z) LANE(w)
    #undef LANE

    __stcs(&x_out[i],    xo);
    __stcs(&low_out[i],  lo);
    __stcs(&high_out[i], ho);
}

extern "C" void kernel_launch(void* const* d_in, const int* in_sizes, int n_in,
                              void* d_out, int out_size)
{
    const float* x    = (const float*)d_in[0];
    const float* low  = (const float*)d_in[1];
    const float* high = (const float*)d_in[2];
    float* out = (float*)d_out;

    const int n  = in_sizes[0];          // 16777216
    const int n4 = n / 4;                // 4194304

    float* x_out    = out;
    float* low_out  = out + n;
    float* high_out = out + 2 * (size_t)n;

    const int threads = 128;
    const int blocks  = (n4 + threads - 1) / threads;  // 32768

    abstract_relu_kernel<<<blocks, threads>>>(
        (const float4*)x, (const float4*)low, (const float4*)high,
        (float4*)x_out, (float4*)low_out, (float4*)high_out, n4);
}